// round 17
// baseline (speedup 1.0000x reference)
#include <cuda_runtime.h>
#include <cstdint>

#define B       8
#define NA      100800
#define NC      85
#define NCLS    80
#define K_PRE   1024
#define MAX_DET 100
#define NBINS   8192
#define CAP     2048
#define CONF    0.25f
#define IOU_T   0.45f
#define MAXWH   7680.0f

// fused kernel geometry
#define S2_ANCH  128                        // anchors per score tile
#define NT2      ((B * NA) / S2_ANCH)       // 6300 tiles
#define T2_B     (S2_ANCH * NC * 4)         // 43520 bytes per tile
#define NSCORE   160                        // score-role blocks
#define BPB      16                         // tail blocks per batch
#define NTAIL    (B * BPB)                  // 128 tail-role blocks
#define GRID2    (NSCORE + NTAIL)           // 288 <= 2*148 -> all co-resident
#define VB       (NA / 4)                   // uint4 per batch
#define VPB      (VB / BPB)                 // 1575 uint4 per gather block

// ---------------- device scratch (no allocations allowed) ----------------
__device__ uint32_t           g_keys[B * NA];
__device__ uint8_t            g_cls [B * NA];
__device__ uint32_t           g_hist[B * NBINS];   // zero-init; re-zeroed in rank phase
__device__ int                g_cnt [B];           // zero-init; reset in finalize
__device__ unsigned int       g_prog[B];           // per-batch completed-tile counters
__device__ unsigned long long g_cand[B * CAP];
__device__ float4             g_bx  [B * K_PRE];
__device__ float              g_area[B * K_PRE];
__device__ float4             g_raw [B * K_PRE];
__device__ float2             g_sc  [B * K_PRE];
__device__ uint32_t           g_maskT[B * 32 * K_PRE];
// per-batch barrier, one 128B line per batch: [0]=count, [1]=generation
__device__ unsigned int       g_bar2[B][32];

// ---------------- mbarrier / TMA-bulk helpers ----------------
__device__ __forceinline__ uint32_t smem_u32(const void* p) {
    return (uint32_t)__cvta_generic_to_shared(p);
}
__device__ __forceinline__ void mbar_init(uint32_t mbar, uint32_t count) {
    asm volatile("mbarrier.init.shared.b64 [%0], %1;" :: "r"(mbar), "r"(count) : "memory");
}
__device__ __forceinline__ void mbar_expect_tx(uint32_t mbar, uint32_t bytes) {
    asm volatile("mbarrier.arrive.expect_tx.shared.b64 _, [%0], %1;"
                 :: "r"(mbar), "r"(bytes) : "memory");
}
__device__ __forceinline__ void bulk_g2s(uint32_t dst, const void* src,
                                         uint32_t bytes, uint32_t mbar) {
    asm volatile("cp.async.bulk.shared::cta.global.mbarrier::complete_tx::bytes "
                 "[%0], [%1], %2, [%3];"
                 :: "r"(dst), "l"(src), "r"(bytes), "r"(mbar) : "memory");
}
__device__ __forceinline__ void mbar_wait(uint32_t mbar, uint32_t phase) {
    uint32_t done;
    asm volatile(
        "{\n\t.reg .pred p;\n\t"
        "mbarrier.try_wait.parity.acquire.cta.shared::cta.b64 p, [%1], %2;\n\t"
        "selp.b32 %0, 1, 0, p;\n\t}"
        : "=r"(done) : "r"(mbar), "r"(phase) : "memory");
    if (!done) {
        asm volatile(
            "{\n\t.reg .pred P1;\n\t"
            "WL_%=:\n\t"
            "mbarrier.try_wait.parity.acquire.cta.shared::cta.b64 P1, [%0], %1, 0x989680;\n\t"
            "@P1 bra.uni WD_%=;\n\t"
            "bra.uni WL_%=;\n\t"
            "WD_%=:\n\t}"
            :: "r"(mbar), "r"(phase) : "memory");
    }
}

// ---------------- per-batch software barrier (16 blocks) ----------------
__device__ __forceinline__ void batch_bar(int b) {
    __syncthreads();
    if (threadIdx.x == 0) {
        __threadfence();
        unsigned int gen = *((volatile unsigned int*)&g_bar2[b][1]);
        unsigned int old = atomicAdd(&g_bar2[b][0], 1u);
        if (old == BPB - 1) {
            *((volatile unsigned int*)&g_bar2[b][0]) = 0u;
            __threadfence();
            atomicAdd(&g_bar2[b][1], 1u);
        } else {
            while (*((volatile unsigned int*)&g_bar2[b][1]) == gen) { }
        }
        __threadfence();
    }
    __syncthreads();
}

// ================= fused kernel: score-role + tail-role, pipelined per batch =================
__global__ void __launch_bounds__(512, 2)
fused_kernel(const float* __restrict__ pred) {
    extern __shared__ float dyn[];              // 87040 B: score tiles / tail staging
    __shared__ alignas(8) unsigned long long barst[2];
    __shared__ int s_ws[33];

    int tid = threadIdx.x;
    int blk = blockIdx.x;
    int lane = tid & 31, wid = tid >> 5;
    const unsigned F = 0xffffffffu;

    if (blk < NSCORE) {
        // ================== SCORE ROLE ==================
        uint32_t sb_u32  = smem_u32(dyn);
        uint32_t bar_u32 = smem_u32(barst);

        if (tid == 0) { mbar_init(bar_u32, 1); mbar_init(bar_u32 + 8, 1); }
        __syncthreads();

        int tile0 = blk;
        if (tile0 < NT2 && tid == 0) {
            mbar_expect_tx(bar_u32, T2_B);
            bulk_g2s(sb_u32, pred + (size_t)tile0 * (S2_ANCH * NC), T2_B, bar_u32);
        }

        int a  = tid >> 2;                      // anchor within tile (0..127)
        int g  = tid & 3;                       // class-quarter (0..3)
        unsigned qmask = 0xFu << (lane & 28);   // this thread's quad

        int ph0 = 0, ph1 = 0;
        int parity = 0;
        for (int tile = tile0; tile < NT2; tile += NSCORE) {
            int next = tile + NSCORE;
            if (next < NT2 && tid == 0) {
                uint32_t b2 = bar_u32 + (parity ^ 1) * 8;
                mbar_expect_tx(b2, T2_B);
                bulk_g2s(sb_u32 + (parity ^ 1) * T2_B,
                         pred + (size_t)next * (S2_ANCH * NC), T2_B, b2);
            }
            if (parity == 0) { mbar_wait(bar_u32,     ph0); ph0 ^= 1; }
            else             { mbar_wait(bar_u32 + 8, ph1); ph1 ^= 1; }

            const float* p = dyn + parity * (S2_ANCH * NC) + a * NC;
            float obj = p[4];
            int anchor = tile * S2_ANCH + a;

            uint32_t key = 0u;
            uint32_t cls = 0u;
            if (obj > CONF) {                   // quad-uniform branch
                // blocked max over classes [20g, 20g+20), strict > : lowest class wins
                float m = -1.f; int bid = 20 * g;
                const float* q = p + 5 + 20 * g;
                #pragma unroll
                for (int k = 0; k < 20; k++) {
                    float c = __fmul_rn(q[k], obj);
                    if (c > m) { m = c; bid = 20 * g + k; }
                }
                // quad merge: global max, lowest class among ties (== sequential merge)
                unsigned bb = __float_as_uint(m);   // m >= 0 -> bits order-monotonic
                #pragma unroll
                for (int o = 1; o <= 2; o <<= 1) {
                    unsigned ob  = __shfl_xor_sync(qmask, bb,  o);
                    int      obd = __shfl_xor_sync(qmask, bid, o);
                    if (ob > bb || (ob == bb && obd < bid)) { bb = ob; bid = obd; }
                }
                if (g == 0) {
                    float best = __uint_as_float(bb);
                    if (best > CONF) {
                        key = bb;
                        cls = (uint32_t)bid;
                        int b = anchor / NA;
                        int bin = (int)(best * (float)NBINS);
                        if (bin > NBINS - 1) bin = NBINS - 1;
                        atomicAdd(&g_hist[b * NBINS + bin], 1u);
                    }
                }
            }
            if (g == 0) {
                g_keys[anchor] = key;
                g_cls [anchor] = (uint8_t)cls;
            }

            __syncthreads();                    // writes done + buffer protect
            if (tid == 0) {
                __threadfence();                // release tile's keys/hist
                int a0 = tile * S2_ANCH;
                int b0 = a0 / NA;
                int b1 = (a0 + S2_ANCH - 1) / NA;
                atomicAdd(&g_prog[b0], 1u);
                if (b1 != b0 && b1 < B) atomicAdd(&g_prog[b1], 1u);
            }
            parity ^= 1;
        }
        return;
    }

    // ================== TAIL ROLE ==================
    int tblk = blk - NSCORE;
    int b_my = tblk >> 4;
    int sub  = tblk & 15;

    // ---- spin until this batch's score is complete ----
    {
        unsigned t0 = (unsigned)(((long long)b_my * NA) >> 7);
        unsigned t1 = (unsigned)((((long long)(b_my + 1) * NA) - 1) >> 7);
        unsigned target = t1 - t0 + 1;
        if (tid == 0) {
            volatile unsigned* vp = &g_prog[b_my];
            while (*vp < target) __nanosleep(1000);
        }
        __syncthreads();
        __threadfence();                        // acquire score's writes
    }

    // ===== phase A: threshold T (512 threads x 16 descending bins) =====
    int T;
    {
        if (tid == 0) s_ws[32] = 0;
        int lo = NBINS - 16 - 16 * tid;
        const uint4* hp = (const uint4*)&g_hist[b_my * NBINS + lo];
        uint4 h0 = hp[0], h1 = hp[1], h2 = hp[2], h3 = hp[3];
        unsigned w[16] = {h0.x,h0.y,h0.z,h0.w, h1.x,h1.y,h1.z,h1.w,
                          h2.x,h2.y,h2.z,h2.w, h3.x,h3.y,h3.z,h3.w};
        int cnts[16]; int ssum = 0;
        #pragma unroll
        for (int k = 0; k < 16; k++) { cnts[k] = (int)w[15 - k]; ssum += cnts[k]; }

        int ps = ssum;
        #pragma unroll
        for (int o = 1; o < 32; o <<= 1) { int v = __shfl_up_sync(F, ps, o); if (lane >= o) ps += v; }
        if (lane == 31) s_ws[wid] = ps;
        __syncthreads();
        if (wid == 0 && lane < 16) {
            int p2 = s_ws[lane];
            #pragma unroll
            for (int o = 1; o < 16; o <<= 1) {
                int u = __shfl_up_sync(0xFFFFu, p2, o);
                if (lane >= o) p2 += u;
            }
            s_ws[lane] = p2;
        }
        __syncthreads();
        int cum  = ps + (wid > 0 ? s_ws[wid - 1] : 0);
        int prev = cum - ssum;
        if (prev < K_PRE && cum >= K_PRE) {
            int acc = prev, TT = 0;
            int base = NBINS - 1 - 16 * tid;
            #pragma unroll
            for (int k = 0; k < 16; k++) { acc += cnts[k]; if (acc >= K_PRE) { TT = base - k; break; } }
            s_ws[32] = TT;
        }
        __syncthreads();
        T = s_ws[32];
        __syncthreads();
    }

    // ===== phase B: gather via smem staging + slot pre-zero =====
    {
        unsigned long long* stage = (unsigned long long*)dyn;   // 16 KB
        int* s_cnt  = &s_ws[0];
        int* s_base = &s_ws[1];
        if (tid == 0) *s_cnt = 0;
        __syncthreads();

        #pragma unroll
        for (int r = 0; r < 4; r++) {
            int v = sub * VPB + r * 512 + tid;
            if (v < (sub + 1) * VPB) {
                uint4 k4 = *(const uint4*)(g_keys + (size_t)b_my * NA + v * 4);
                uint32_t kk[4] = {k4.x, k4.y, k4.z, k4.w};
                #pragma unroll
                for (int u = 0; u < 4; u++) {
                    uint32_t key = kk[u];
                    if (!key) continue;
                    float s = __uint_as_float(key);
                    int bin = (int)(s * (float)NBINS);
                    if (bin > NBINS - 1) bin = NBINS - 1;
                    if (bin < T) continue;
                    int p = atomicAdd(s_cnt, 1);
                    if (p < CAP) {
                        uint32_t li = (uint32_t)(v * 4 + u);
                        stage[p] = ((unsigned long long)key << 32) |
                                   (unsigned long long)(0xFFFFFFFFu - li);
                    }
                }
            }
        }
        __syncthreads();
        int scnt = *s_cnt; if (scnt > CAP) scnt = CAP;
        if (tid == 0) *s_base = (scnt > 0) ? atomicAdd(&g_cnt[b_my], scnt) : 0;
        __syncthreads();
        int sbase = *s_base;
        for (int i = tid; i < scnt; i += 512) {
            int gpos = sbase + i;
            if (gpos < CAP) g_cand[b_my * CAP + gpos] = stage[i];
        }
        // per-batch slot pre-zero: 16 blocks x 64 slots
        if (tid < 64) {
            int s = b_my * K_PRE + sub * 64 + tid;
            g_sc  [s] = make_float2(0.f, 0.f);
            g_bx  [s] = make_float4(0.f, 0.f, 0.f, 0.f);
            g_area[s] = 0.f;
        }
    }
    batch_bar(b_my);

    // progress counter reset (all 16 blocks past spin; next score run is next replay)
    if (sub == 0 && tid == 0) g_prog[b_my] = 0u;

    // ===== phase C: rank (16 warps x 8 candidates) + hist re-zero + maskT zero =====
    {
        if (tid < 512) g_hist[b_my * NBINS + sub * 512 + tid] = 0u;
        {
            uint2* mz = (uint2*)&g_maskT[(size_t)b_my * 32 * K_PRE];
            #pragma unroll
            for (int r = 0; r < 2; r++)
                mz[sub * 1024 + r * 512 + tid] = make_uint2(0u, 0u);
        }

        unsigned long long* sk = (unsigned long long*)dyn;      // 16 KB (reuse)
        int cnt = g_cnt[b_my];
        if (cnt > CAP) cnt = CAP;
        int cntP = (cnt + 127) & ~127;

        if (sub * 128 < cnt) {
            for (int j = tid; j < cntP; j += 512)
                sk[j] = (j < cnt) ? g_cand[b_my * CAP + j] : 0ull;
            __syncthreads();

            int ibase = sub * 128 + wid * 8;
            unsigned long long kK[8];
            bool vK[8];
            #pragma unroll
            for (int k = 0; k < 8; k++) {
                vK[k] = (ibase + k) < cnt;
                kK[k] = vK[k] ? sk[ibase + k] : ~0ull;
            }

            int cK[8] = {0,0,0,0,0,0,0,0};
            for (int j = lane; j < cntP; j += 32) {
                unsigned long long v = sk[j];
                #pragma unroll
                for (int k = 0; k < 8; k++) cK[k] += (v > kK[k]);
            }
            int rK[8];
            #pragma unroll
            for (int k = 0; k < 8; k++) rK[k] = __reduce_add_sync(F, cK[k]);

            #pragma unroll
            for (int k = 0; k < 8; k++) {
                if (lane == k && vK[k] && rK[k] < K_PRE) {
                    unsigned long long ki = kK[k];
                    int rank = rK[k];
                    float score = __uint_as_float((uint32_t)(ki >> 32));
                    uint32_t idx = 0xFFFFFFFFu - (uint32_t)ki;

                    const float* pr = pred + ((size_t)b_my * NA + idx) * NC;
                    float cx = pr[0], cy = pr[1], w = pr[2], h = pr[3];
                    float x1 = __fsub_rn(cx, __fmul_rn(w, 0.5f));
                    float y1 = __fsub_rn(cy, __fmul_rn(h, 0.5f));
                    float x2 = __fadd_rn(cx, __fmul_rn(w, 0.5f));
                    float y2 = __fadd_rn(cy, __fmul_rn(h, 0.5f));
                    float clsf = (float)g_cls[b_my * NA + idx];
                    float off  = __fmul_rn(clsf, MAXWH);
                    float ox1 = __fadd_rn(x1, off), oy1 = __fadd_rn(y1, off);
                    float ox2 = __fadd_rn(x2, off), oy2 = __fadd_rn(y2, off);

                    int s = b_my * K_PRE + rank;
                    g_bx  [s] = make_float4(ox1, oy1, ox2, oy2);
                    g_area[s] = __fmul_rn(__fsub_rn(ox2, ox1), __fsub_rn(oy2, oy1));
                    g_raw [s] = make_float4(x1, y1, x2, y2);
                    g_sc  [s] = make_float2(score, clsf);
                }
            }
        }
    }
}

// ================= finalize: per-class IoU + Jacobi + output (one block/batch) =================
__global__ void __launch_bounds__(1024, 1)
finalize_kernel(float* __restrict__ out) {
    __shared__ float4   jb4[K_PRE];
    __shared__ float    ja [K_PRE];
    __shared__ int      ccnt[NCLS];
    __shared__ int      cbase[NCLS + 1];
    __shared__ uint16_t clist[K_PRE];
    __shared__ uint32_t keep_s[32];
    __shared__ int      pfx[33];

    int b   = blockIdx.x;
    int tid = threadIdx.x;
    int lane = tid & 31, wid = tid >> 5;
    const unsigned F = 0xffffffffu;

    if (tid == 0) g_cnt[b] = 0;                 // reset for next replay
    if (tid < MAX_DET * 6) out[b * MAX_DET * 6 + tid] = 0.0f;

    jb4[tid] = g_bx  [b * K_PRE + tid];
    ja [tid] = g_area[b * K_PRE + tid];
    float2 sc = g_sc[b * K_PRE + tid];
    bool valid = sc.x > 0.0f;
    int  cls   = (int)sc.y;

    if (tid < NCLS) ccnt[tid] = 0;
    __syncthreads();
    int mypos = -1;
    if (valid) mypos = atomicAdd(&ccnt[cls], 1);
    __syncthreads();
    if (tid == 0) {
        int s = 0;
        for (int c = 0; c < NCLS; c++) { cbase[c] = s; s += ccnt[c]; }
        cbase[NCLS] = s;
    }
    __syncthreads();
    if (valid) clist[cbase[cls] + mypos] = (uint16_t)tid;
    __syncthreads();

    // same-class suppression only (cross-class IoU is exactly 0 by offset)
    if (valid) {
        float4 ib = jb4[tid];
        float  ia = ja [tid];
        int s0 = cbase[cls], s1 = cbase[cls + 1];
        for (int q = s0; q < s1; q++) {
            int r = clist[q];
            if (r >= tid) continue;
            float4 ob = jb4[r];
            float ltx = fmaxf(ib.x, ob.x), lty = fmaxf(ib.y, ob.y);
            float rbx = fminf(ib.z, ob.z), rby = fminf(ib.w, ob.w);
            float ww = fmaxf(__fsub_rn(rbx, ltx), 0.0f);
            float hh = fmaxf(__fsub_rn(rby, lty), 0.0f);
            float inter = __fmul_rn(ww, hh);
            float uni   = __fadd_rn(__fsub_rn(__fadd_rn(ia, ja[r]), inter), 1e-7f);
            float iou   = __fdiv_rn(inter, uni);
            if (iou > IOU_T)
                atomicOr(&g_maskT[(b * 32 + (r >> 5)) * K_PRE + tid], 1u << (r & 31));
        }
    }
    __syncthreads();

    uint32_t row[32];
    #pragma unroll
    for (int w = 0; w < 32; w++) row[w] = g_maskT[(b * 32 + w) * K_PRE + tid];

    {
        unsigned bal = __ballot_sync(F, valid);
        if (lane == 0) keep_s[wid] = bal;
    }
    __syncthreads();

    for (int it = 0; it < K_PRE; it++) {
        uint32_t acc = 0;
        #pragma unroll
        for (int w = 0; w < 32; w++) acc |= row[w] & keep_s[w];
        int nb  = (valid && acc == 0) ? 1 : 0;
        int old = (keep_s[wid] >> lane) & 1;
        __syncthreads();
        unsigned nbal = __ballot_sync(F, nb);
        if (lane == 0) keep_s[wid] = nbal;
        int changed = __syncthreads_or(nb != old);
        if (!changed) break;
    }

    if (tid == 0) {
        pfx[0] = 0;
        for (int w = 0; w < 32; w++) pfx[w + 1] = pfx[w] + __popc(keep_s[w]);
    }
    __syncthreads();

    uint32_t kw = keep_s[wid];
    if (valid && ((kw >> lane) & 1)) {
        int rank = pfx[wid] + __popc(kw & ((1u << lane) - 1u));
        if (rank < MAX_DET) {
            float4 r = g_raw[b * K_PRE + tid];
            float* o = out + ((size_t)b * MAX_DET + rank) * 6;
            o[0] = r.x; o[1] = r.y; o[2] = r.z; o[3] = r.w;
            o[4] = sc.x; o[5] = sc.y;
        }
    }
}

// ---------------- launcher ----------------
extern "C" void kernel_launch(void* const* d_in, const int* in_sizes, int n_in,
                              void* d_out, int out_size) {
    (void)in_sizes; (void)n_in; (void)out_size;
    const float* pred = (const float*)d_in[0];
    float* out = (float*)d_out;

    static int configured = 0;
    if (!configured) {
        cudaFuncSetAttribute(fused_kernel,
                             cudaFuncAttributeMaxDynamicSharedMemorySize, 2 * T2_B);
        configured = 1;
    }

    fused_kernel   <<<GRID2, 512, 2 * T2_B>>>(pred);
    finalize_kernel<<<B, 1024>>>(out);
}